// round 1
// baseline (speedup 1.0000x reference)
#include <cuda_runtime.h>
#include <math.h>

// Fused flash-attention, fp32 SIMT baseline.
// S=8192, D=128. out = softmax(q k^T / sqrt(D)) @ v
//
// CTA: BM=64 query rows, 256 threads, iterates over 128 K/V tiles of BN=64.
// Warp tile 16x32 (lanes 4x8, per-thread 4x4 scores), O block 4 rows x 8 cols.
// Online softmax with row stats in smem.

namespace {
constexpr int S_TOTAL  = 8192;
constexpr int D_DIM    = 128;
constexpr int BM       = 64;
constexpr int BN       = 64;
constexpr int NTHREADS = 256;
constexpr int QK_STRIDE = 132;  // padded row stride (floats): bank-shift 4, 16B aligned
constexpr int P_STRIDE  = 68;   // padded P row stride
constexpr int NTILES    = S_TOTAL / BN;

constexpr int SMEM_FLOATS =
    BM * QK_STRIDE +   // Qs
    BN * QK_STRIDE +   // Ks
    BN * QK_STRIDE +   // Vs
    BM * P_STRIDE  +   // Ps
    BM * 16        +   // red
    BM * 3;            // row_m, row_l, row_scale
}  // namespace

__global__ __launch_bounds__(NTHREADS, 1)
void flash_attn_f32_kernel(const float* __restrict__ gq,
                           const float* __restrict__ gk,
                           const float* __restrict__ gv,
                           float* __restrict__ gout) {
    extern __shared__ float sm[];
    float* Qs        = sm;
    float* Ks        = Qs + BM * QK_STRIDE;
    float* Vs        = Ks + BN * QK_STRIDE;
    float* Ps        = Vs + BN * QK_STRIDE;
    float* red       = Ps + BM * P_STRIDE;
    float* row_m     = red + BM * 16;
    float* row_l     = row_m + BM;
    float* row_scale = row_l + BM;

    const int tid  = threadIdx.x;
    const int lane = tid & 31;
    const int warp = tid >> 5;
    const int wr   = warp & 3;      // warp row block (4)
    const int wc   = warp >> 2;     // warp col block (2)
    const int lr   = lane >> 3;     // lane row (4)
    const int lc   = lane & 7;      // lane col (8)

    const int r0   = wr * 16 + lr * 4;   // 4 score rows owned by this thread
    const int c0   = wc * 32 + lc * 4;   // 4 score cols
    const int redx = wc * 8 + lc;        // 0..15 reduction slot
    const int oc0  = redx * 8;           // 8 O columns

    const int qbase = blockIdx.x * BM;

    // ---- load Q tile (once) ----
#pragma unroll
    for (int it = 0; it < (BM * D_DIM / 4) / NTHREADS; ++it) {
        int idx = it * NTHREADS + tid;
        int row = idx >> 5;          // D/4 = 32 float4 per row
        int c4  = idx & 31;
        float4 val = reinterpret_cast<const float4*>(gq)[(size_t)(qbase + row) * (D_DIM / 4) + c4];
        *reinterpret_cast<float4*>(&Qs[row * QK_STRIDE + c4 * 4]) = val;
    }
    if (tid < BM) { row_m[tid] = -INFINITY; row_l[tid] = 0.0f; }

    float acc_o[4][8];
#pragma unroll
    for (int i = 0; i < 4; ++i)
#pragma unroll
        for (int j = 0; j < 8; ++j) acc_o[i][j] = 0.0f;

    const float sm_scale = 0.08838834764831845f;  // 1/sqrt(128)

    for (int t = 0; t < NTILES; ++t) {
        __syncthreads();  // protect Ks/Vs/Ps/red from previous iteration readers
        const int kb = t * BN;
#pragma unroll
        for (int it = 0; it < (BN * D_DIM / 4) / NTHREADS; ++it) {
            int idx = it * NTHREADS + tid;
            int row = idx >> 5;
            int c4  = idx & 31;
            float4 kv = reinterpret_cast<const float4*>(gk)[(size_t)(kb + row) * (D_DIM / 4) + c4];
            *reinterpret_cast<float4*>(&Ks[row * QK_STRIDE + c4 * 4]) = kv;
            float4 vv = reinterpret_cast<const float4*>(gv)[(size_t)(kb + row) * (D_DIM / 4) + c4];
            *reinterpret_cast<float4*>(&Vs[row * QK_STRIDE + c4 * 4]) = vv;
        }
        __syncthreads();

        // ---- S = Q K^T ----
        float acc_s[4][4];
#pragma unroll
        for (int i = 0; i < 4; ++i)
#pragma unroll
            for (int j = 0; j < 4; ++j) acc_s[i][j] = 0.0f;

#pragma unroll 4
        for (int kk = 0; kk < D_DIM; kk += 4) {
            float4 qv[4], kv[4];
#pragma unroll
            for (int i = 0; i < 4; ++i)
                qv[i] = *reinterpret_cast<const float4*>(&Qs[(r0 + i) * QK_STRIDE + kk]);
#pragma unroll
            for (int j = 0; j < 4; ++j)
                kv[j] = *reinterpret_cast<const float4*>(&Ks[(c0 + j) * QK_STRIDE + kk]);
#pragma unroll
            for (int i = 0; i < 4; ++i)
#pragma unroll
                for (int j = 0; j < 4; ++j) {
                    acc_s[i][j] += qv[i].x * kv[j].x;
                    acc_s[i][j] += qv[i].y * kv[j].y;
                    acc_s[i][j] += qv[i].z * kv[j].z;
                    acc_s[i][j] += qv[i].w * kv[j].w;
                }
        }

        // scale + per-thread row max
#pragma unroll
        for (int i = 0; i < 4; ++i) {
            float lm = -INFINITY;
#pragma unroll
            for (int j = 0; j < 4; ++j) {
                acc_s[i][j] *= sm_scale;
                lm = fmaxf(lm, acc_s[i][j]);
            }
            red[(r0 + i) * 16 + redx] = lm;
        }
        __syncthreads();

        if (tid < BM) {
            float m_old = row_m[tid];
            float tm = red[tid * 16];
#pragma unroll
            for (int x = 1; x < 16; ++x) tm = fmaxf(tm, red[tid * 16 + x]);
            float m_new = fmaxf(m_old, tm);
            row_scale[tid] = __expf(m_old - m_new);  // exp(-inf)=0 on first tile
            row_m[tid] = m_new;
        }
        __syncthreads();

        // ---- exp, store P, partial row sums ----
#pragma unroll
        for (int i = 0; i < 4; ++i) {
            float m = row_m[r0 + i];
            float s = 0.0f;
#pragma unroll
            for (int j = 0; j < 4; ++j) {
                float p = __expf(acc_s[i][j] - m);
                Ps[(r0 + i) * P_STRIDE + (c0 + j)] = p;
                s += p;
            }
            red[(r0 + i) * 16 + redx] = s;
        }
        __syncthreads();

        if (tid < BM) {
            float s = 0.0f;
#pragma unroll
            for (int x = 0; x < 16; ++x) s += red[tid * 16 + x];
            row_l[tid] = row_l[tid] * row_scale[tid] + s;
        }

        // ---- rescale O, accumulate P @ V ----
        float f[4];
#pragma unroll
        for (int i = 0; i < 4; ++i) f[i] = row_scale[r0 + i];
#pragma unroll
        for (int i = 0; i < 4; ++i)
#pragma unroll
            for (int j = 0; j < 8; ++j) acc_o[i][j] *= f[i];

#pragma unroll 4
        for (int jj = 0; jj < BN; jj += 4) {
            float4 pv[4];
#pragma unroll
            for (int i = 0; i < 4; ++i)
                pv[i] = *reinterpret_cast<const float4*>(&Ps[(r0 + i) * P_STRIDE + jj]);
#pragma unroll
            for (int q = 0; q < 4; ++q) {
                float4 va = *reinterpret_cast<const float4*>(&Vs[(jj + q) * QK_STRIDE + oc0]);
                float4 vb = *reinterpret_cast<const float4*>(&Vs[(jj + q) * QK_STRIDE + oc0 + 4]);
#pragma unroll
                for (int i = 0; i < 4; ++i) {
                    float p = (q == 0) ? pv[i].x : (q == 1) ? pv[i].y : (q == 2) ? pv[i].z : pv[i].w;
                    acc_o[i][0] += p * va.x;
                    acc_o[i][1] += p * va.y;
                    acc_o[i][2] += p * va.z;
                    acc_o[i][3] += p * va.w;
                    acc_o[i][4] += p * vb.x;
                    acc_o[i][5] += p * vb.y;
                    acc_o[i][6] += p * vb.z;
                    acc_o[i][7] += p * vb.w;
                }
            }
        }
    }

    __syncthreads();

    // ---- normalize + write out ----
#pragma unroll
    for (int i = 0; i < 4; ++i) {
        float inv = 1.0f / row_l[r0 + i];
        float4 oa, ob;
        oa.x = acc_o[i][0] * inv; oa.y = acc_o[i][1] * inv;
        oa.z = acc_o[i][2] * inv; oa.w = acc_o[i][3] * inv;
        ob.x = acc_o[i][4] * inv; ob.y = acc_o[i][5] * inv;
        ob.z = acc_o[i][6] * inv; ob.w = acc_o[i][7] * inv;
        size_t base = (size_t)(qbase + r0 + i) * D_DIM + oc0;
        *reinterpret_cast<float4*>(&gout[base])     = oa;
        *reinterpret_cast<float4*>(&gout[base + 4]) = ob;
    }
}

extern "C" void kernel_launch(void* const* d_in, const int* in_sizes, int n_in,
                              void* d_out, int out_size) {
    const float* q = (const float*)d_in[0];
    const float* k = (const float*)d_in[1];
    const float* v = (const float*)d_in[2];
    float* out = (float*)d_out;
    (void)in_sizes; (void)n_in; (void)out_size;

    const int smem_bytes = SMEM_FLOATS * (int)sizeof(float);  // ~120.8 KB
    cudaFuncSetAttribute(flash_attn_f32_kernel,
                         cudaFuncAttributeMaxDynamicSharedMemorySize, smem_bytes);
    flash_attn_f32_kernel<<<S_TOTAL / BM, NTHREADS, smem_bytes>>>(q, k, v, out);
}

// round 3
// speedup vs baseline: 2.0915x; 2.0915x over previous
#include <cuda_runtime.h>
#include <math.h>
#include <stdint.h>

// Flash attention, tensor-core tf32 (split hi/lo for ~fp32 accuracy).
// S=8192, D=128. out = softmax(q k^T / sqrt(D)) @ v
// CTA: 256 threads (8 warps), BM=64 query rows, loop over 128 K/V tiles (BN=64).
// QK^T: warp grid 4(row)x2(col): each warp m16 x n32, K=128 (16 k-steps of 8).
// PV  : each warp m16 x n64 (d-half), K=64 (8 k-steps of 8).
// Every matmul uses mma.sync.m16n8k8 tf32 with 2-term split (3 MMAs/product).
// V stored straight (s-major, stride 136): PV B-fragment = two conflict-free LDS.32.

namespace {
constexpr int S_TOTAL  = 8192;
constexpr int D_DIM    = 128;
constexpr int BM       = 64;
constexpr int BN       = 64;
constexpr int NTHREADS = 256;
constexpr int QK_STRIDE = 132;   // Qs/Ks row stride (floats), even -> float2-safe
constexpr int VS_STRIDE = 136;   // Vs row stride: bank(s,d) = 8*(s&3)+d&7 pattern, conflict-free frag reads
constexpr int P_STRIDE  = 68;    // Ps row stride
constexpr int NTILES    = S_TOTAL / BN;

constexpr int OFF_Q     = 0;
constexpr int OFF_K     = OFF_Q + BM * QK_STRIDE;
constexpr int OFF_V     = OFF_K + BN * QK_STRIDE;
constexpr int OFF_P     = OFF_V + BN * VS_STRIDE;
constexpr int OFF_RM    = OFF_P + BM * P_STRIDE;     // red max [64][2]
constexpr int OFF_RS    = OFF_RM + BM * 2;           // red sum [64][2]
constexpr int OFF_ROWM  = OFF_RS + BM * 2;
constexpr int OFF_ROWL  = OFF_ROWM + BM;
constexpr int OFF_ROWSC = OFF_ROWL + BM;
constexpr int SMEM_FLOATS = OFF_ROWSC + BM;          // ~30.4K floats = ~122 KB
}  // namespace

__device__ __forceinline__ int perm8(int c) {
    // maps col c so that pairs (c, c+4) within an 8-block become adjacent
    return ((c & 3) << 1) | ((c >> 2) & 1);
}

__device__ __forceinline__ void split_tf32(float x, uint32_t& hi, uint32_t& lo) {
    uint32_t h;
    asm("cvt.rna.tf32.f32 %0, %1;" : "=r"(h) : "f"(x));
    float r = x - __uint_as_float(h);
    asm("cvt.rna.tf32.f32 %0, %1;" : "=r"(lo) : "f"(r));
    hi = h;
}

__device__ __forceinline__ void mma8(float* c,
                                     uint32_t a0, uint32_t a1, uint32_t a2, uint32_t a3,
                                     uint32_t b0, uint32_t b1) {
    asm volatile(
        "mma.sync.aligned.m16n8k8.row.col.f32.tf32.tf32.f32 "
        "{%0,%1,%2,%3}, {%4,%5,%6,%7}, {%8,%9}, {%0,%1,%2,%3};\n"
        : "+f"(c[0]), "+f"(c[1]), "+f"(c[2]), "+f"(c[3])
        : "r"(a0), "r"(a1), "r"(a2), "r"(a3), "r"(b0), "r"(b1));
}

// 3-term split MMA: C += Ahi*Bhi + Ahi*Blo + Alo*Bhi
__device__ __forceinline__ void mma8_split(float* c,
                                           const uint32_t ah[4], const uint32_t al[4],
                                           uint32_t bh0, uint32_t bh1,
                                           uint32_t bl0, uint32_t bl1) {
    mma8(c, ah[0], ah[1], ah[2], ah[3], bh0, bh1);
    mma8(c, ah[0], ah[1], ah[2], ah[3], bl0, bl1);
    mma8(c, al[0], al[1], al[2], al[3], bh0, bh1);
}

__device__ __forceinline__ void store_perm4(float* row_base, int c4, float4 v) {
    int blk = (c4 * 4) & ~7;
    int lo4 = (c4 & 1) * 4;
    row_base[blk + perm8(lo4 + 0)] = v.x;
    row_base[blk + perm8(lo4 + 1)] = v.y;
    row_base[blk + perm8(lo4 + 2)] = v.z;
    row_base[blk + perm8(lo4 + 3)] = v.w;
}

__global__ __launch_bounds__(NTHREADS, 1)
void fa_tf32_kernel(const float* __restrict__ gq,
                    const float* __restrict__ gk,
                    const float* __restrict__ gv,
                    float* __restrict__ gout) {
    extern __shared__ float sm[];
    float* Qs     = sm + OFF_Q;
    float* Ks     = sm + OFF_K;
    float* Vs     = sm + OFF_V;
    float* Ps     = sm + OFF_P;
    float* red_m  = sm + OFF_RM;
    float* red_s  = sm + OFF_RS;
    float* row_m  = sm + OFF_ROWM;
    float* row_l  = sm + OFF_ROWL;
    float* row_sc = sm + OFF_ROWSC;

    const int tid  = threadIdx.x;
    const int lane = tid & 31;
    const int warp = tid >> 5;
    const int wr   = warp & 3;       // warp row group: rows [wr*16, wr*16+16)
    const int wc   = warp >> 2;      // warp col half
    const int lq   = lane & 3;       // thread-in-group (k / col index)
    const int lr   = lane >> 2;      // group id (row 0..7)
    const int m0   = wr * 16;
    const int r0   = m0 + lr;        // rows r0 and r0+8 owned by this thread

    const int qbase = blockIdx.x * BM;
    const float4* gq4 = reinterpret_cast<const float4*>(gq);
    const float4* gk4 = reinterpret_cast<const float4*>(gk);
    const float4* gv4 = reinterpret_cast<const float4*>(gv);

    // ---- load Q tile once (perm cols) ----
#pragma unroll
    for (int it = 0; it < (BM * D_DIM / 4) / NTHREADS; ++it) {
        int idx = it * NTHREADS + tid;
        int row = idx >> 5;
        int c4  = idx & 31;
        float4 v = gq4[(size_t)(qbase + row) * (D_DIM / 4) + c4];
        store_perm4(&Qs[row * QK_STRIDE], c4, v);
    }
    if (tid < BM) { row_m[tid] = -INFINITY; row_l[tid] = 0.0f; }

    float acc_o[8][4];
#pragma unroll
    for (int n = 0; n < 8; ++n)
#pragma unroll
        for (int j = 0; j < 4; ++j) acc_o[n][j] = 0.0f;

    const float sm_scale = 0.08838834764831845f;  // 1/sqrt(128)

    for (int t = 0; t < NTILES; ++t) {
        __syncthreads();  // protect Ks/Vs/Ps/red from previous tile readers
        const int kb = t * BN;

        // ---- load K (perm cols) and V (straight, s-major) ----
#pragma unroll
        for (int it = 0; it < (BN * D_DIM / 4) / NTHREADS; ++it) {
            int idx = it * NTHREADS + tid;
            int row = idx >> 5;
            int c4  = idx & 31;
            float4 v = gk4[(size_t)(kb + row) * (D_DIM / 4) + c4];
            store_perm4(&Ks[row * QK_STRIDE], c4, v);
        }
#pragma unroll
        for (int it = 0; it < (BN * D_DIM / 4) / NTHREADS; ++it) {
            int idx = it * NTHREADS + tid;
            int s   = idx >> 5;
            int c4  = idx & 31;
            float4 v = gv4[(size_t)(kb + s) * (D_DIM / 4) + c4];
            *reinterpret_cast<float4*>(&Vs[s * VS_STRIDE + c4 * 4]) = v;
        }
        __syncthreads();

        // ---- S = Q K^T (split tf32 mma) ----
        float sc[4][4];
#pragma unroll
        for (int n = 0; n < 4; ++n)
#pragma unroll
            for (int j = 0; j < 4; ++j) sc[n][j] = 0.0f;

#pragma unroll
        for (int ks = 0; ks < D_DIM / 8; ++ks) {
            const int k0 = ks * 8;
            float2 qa = *reinterpret_cast<const float2*>(&Qs[r0 * QK_STRIDE + k0 + 2 * lq]);
            float2 qb = *reinterpret_cast<const float2*>(&Qs[(r0 + 8) * QK_STRIDE + k0 + 2 * lq]);
            uint32_t ah[4], al[4];
            split_tf32(qa.x, ah[0], al[0]);
            split_tf32(qb.x, ah[1], al[1]);
            split_tf32(qa.y, ah[2], al[2]);
            split_tf32(qb.y, ah[3], al[3]);
#pragma unroll
            for (int nt = 0; nt < 4; ++nt) {
                const int n0 = wc * 32 + nt * 8;
                float2 kv = *reinterpret_cast<const float2*>(&Ks[(n0 + lr) * QK_STRIDE + k0 + 2 * lq]);
                uint32_t bh0, bl0, bh1, bl1;
                split_tf32(kv.x, bh0, bl0);
                split_tf32(kv.y, bh1, bl1);
                mma8_split(sc[nt], ah, al, bh0, bh1, bl0, bl1);
            }
        }

        // ---- softmax stats ----
        float mr = -INFINITY, mr8 = -INFINITY;
#pragma unroll
        for (int nt = 0; nt < 4; ++nt) {
            sc[nt][0] *= sm_scale; sc[nt][1] *= sm_scale;
            sc[nt][2] *= sm_scale; sc[nt][3] *= sm_scale;
            mr  = fmaxf(mr,  fmaxf(sc[nt][0], sc[nt][1]));
            mr8 = fmaxf(mr8, fmaxf(sc[nt][2], sc[nt][3]));
        }
        mr  = fmaxf(mr,  __shfl_xor_sync(0xffffffffu, mr, 1));
        mr  = fmaxf(mr,  __shfl_xor_sync(0xffffffffu, mr, 2));
        mr8 = fmaxf(mr8, __shfl_xor_sync(0xffffffffu, mr8, 1));
        mr8 = fmaxf(mr8, __shfl_xor_sync(0xffffffffu, mr8, 2));
        if (lq == 0) {
            red_m[r0 * 2 + wc]       = mr;
            red_m[(r0 + 8) * 2 + wc] = mr8;
        }
        __syncthreads();

        if (tid < BM) {
            float mo = row_m[tid];
            float mn = fmaxf(mo, fmaxf(red_m[tid * 2], red_m[tid * 2 + 1]));
            row_m[tid]  = mn;
            row_sc[tid] = __expf(mo - mn);  // 0 on first tile
        }
        __syncthreads();

        // ---- exp, write P (perm cols), partial row sums ----
        const float mrow  = row_m[r0];
        const float mrow8 = row_m[r0 + 8];
        float s_r = 0.0f, s_r8 = 0.0f;
        const int o0 = perm8(2 * lq);
        const int o1 = perm8(2 * lq + 1);
#pragma unroll
        for (int nt = 0; nt < 4; ++nt) {
            const int cb = wc * 32 + nt * 8;
            float p00 = __expf(sc[nt][0] - mrow);
            float p01 = __expf(sc[nt][1] - mrow);
            float p10 = __expf(sc[nt][2] - mrow8);
            float p11 = __expf(sc[nt][3] - mrow8);
            s_r  += p00 + p01;
            s_r8 += p10 + p11;
            Ps[r0 * P_STRIDE + cb + o0]       = p00;
            Ps[r0 * P_STRIDE + cb + o1]       = p01;
            Ps[(r0 + 8) * P_STRIDE + cb + o0] = p10;
            Ps[(r0 + 8) * P_STRIDE + cb + o1] = p11;
        }
        s_r  += __shfl_xor_sync(0xffffffffu, s_r, 1);
        s_r  += __shfl_xor_sync(0xffffffffu, s_r, 2);
        s_r8 += __shfl_xor_sync(0xffffffffu, s_r8, 1);
        s_r8 += __shfl_xor_sync(0xffffffffu, s_r8, 2);
        if (lq == 0) {
            red_s[r0 * 2 + wc]       = s_r;
            red_s[(r0 + 8) * 2 + wc] = s_r8;
        }

        // rescale O accumulators
        const float f0 = row_sc[r0];
        const float f1 = row_sc[r0 + 8];
#pragma unroll
        for (int nt = 0; nt < 8; ++nt) {
            acc_o[nt][0] *= f0; acc_o[nt][1] *= f0;
            acc_o[nt][2] *= f1; acc_o[nt][3] *= f1;
        }
        __syncthreads();

        if (tid < BM)
            row_l[tid] = row_l[tid] * row_sc[tid] + red_s[tid * 2] + red_s[tid * 2 + 1];

        // ---- O += P V (split tf32 mma), warp covers d-half of 64 ----
#pragma unroll
        for (int ks = 0; ks < BN / 8; ++ks) {
            const int k0 = ks * 8;
            float2 pa = *reinterpret_cast<const float2*>(&Ps[r0 * P_STRIDE + k0 + 2 * lq]);
            float2 pb = *reinterpret_cast<const float2*>(&Ps[(r0 + 8) * P_STRIDE + k0 + 2 * lq]);
            uint32_t ah[4], al[4];
            split_tf32(pa.x, ah[0], al[0]);
            split_tf32(pb.x, ah[1], al[1]);
            split_tf32(pa.y, ah[2], al[2]);
            split_tf32(pb.y, ah[3], al[3]);
#pragma unroll
            for (int nt = 0; nt < 8; ++nt) {
                const int n0 = wc * 64 + nt * 8;
                // B fragment: V[k0+lq][n0+lr], V[k0+lq+4][n0+lr] -- two scalar LDS.32,
                // bank = (8*lq + lr) mod 32 across the warp: conflict-free.
                float v0 = Vs[(k0 + lq) * VS_STRIDE + n0 + lr];
                float v1 = Vs[(k0 + lq + 4) * VS_STRIDE + n0 + lr];
                uint32_t bh0, bl0, bh1, bl1;
                split_tf32(v0, bh0, bl0);
                split_tf32(v1, bh1, bl1);
                mma8_split(acc_o[nt], ah, al, bh0, bh1, bl0, bl1);
            }
        }
    }

    __syncthreads();

    // ---- normalize + store ----
    const float inv0 = 1.0f / row_l[r0];
    const float inv1 = 1.0f / row_l[r0 + 8];
#pragma unroll
    for (int nt = 0; nt < 8; ++nt) {
        const int d0 = wc * 64 + nt * 8 + 2 * lq;
        float2 oa, ob;
        oa.x = acc_o[nt][0] * inv0; oa.y = acc_o[nt][1] * inv0;
        ob.x = acc_o[nt][2] * inv1; ob.y = acc_o[nt][3] * inv1;
        *reinterpret_cast<float2*>(&gout[(size_t)(qbase + r0) * D_DIM + d0])     = oa;
        *reinterpret_cast<float2*>(&gout[(size_t)(qbase + r0 + 8) * D_DIM + d0]) = ob;
    }
}

extern "C" void kernel_launch(void* const* d_in, const int* in_sizes, int n_in,
                              void* d_out, int out_size) {
    const float* q = (const float*)d_in[0];
    const float* k = (const float*)d_in[1];
    const float* v = (const float*)d_in[2];
    float* out = (float*)d_out;
    (void)in_sizes; (void)n_in; (void)out_size;

    const int smem_bytes = SMEM_FLOATS * (int)sizeof(float);
    cudaFuncSetAttribute(fa_tf32_kernel,
                         cudaFuncAttributeMaxDynamicSharedMemorySize, smem_bytes);
    fa_tf32_kernel<<<S_TOTAL / BM, NTHREADS, smem_bytes>>>(q, k, v, out);
}